// round 4
// baseline (speedup 1.0000x reference)
#include <cuda_runtime.h>

#define NN   50000
#define EE   800000
#define HIDD 128
#define OUTD 4

// ---------------- scratch (static device globals; no runtime allocation) ----
__device__ float g_hA[(size_t)NN * HIDD];
__device__ float g_hB[(size_t)NN * HIDD];
__device__ float g_L[NN];
__device__ float g_R[NN];
__device__ int   g_cnt[NN];
__device__ int   g_cursor[NN];
__device__ int   g_start[NN + 1];
__device__ int   g_csrc[EE];
__device__ float g_P[NN * OUTD];
__device__ float g_Q[NN * OUTD];

// ---------------- GEMM  H = X @ W  (M=50000, K=128, N=128) + L/R epilogue ---
// 128x128 tile, 256 threads, 8x8 per thread, Xs stored k-major for LDS.128
__global__ __launch_bounds__(256) void gemm_lr_kernel(
        const float* __restrict__ X, const float* __restrict__ W,
        const float* __restrict__ attl, const float* __restrict__ attr,
        float* __restrict__ H, float* __restrict__ Lo, float* __restrict__ Ro) {
    __shared__ float Xs[32][128];   // [k][m]  16 KB
    __shared__ float Ws[32][128];   // [k][n]  16 KB
    const int tid = threadIdx.x;
    const int tx = tid & 15;        // col group (8 cols)
    const int ty = tid >> 4;        // row group (8 rows)
    const int row0 = blockIdx.x * 128;
    const int lrow  = tid & 127;    // X-load row
    const int lhalf = tid >> 7;     // X-load k half (0/1)

    float acc[8][8];
#pragma unroll
    for (int i = 0; i < 8; i++)
#pragma unroll
        for (int j = 0; j < 8; j++) acc[i][j] = 0.f;

    for (int kc = 0; kc < HIDD; kc += 32) {
        // X tile: 128 rows x 32 k, transposed into Xs[k][m]
        {
            int grow = row0 + lrow;
#pragma unroll
            for (int q = 0; q < 4; q++) {
                int k = lhalf * 16 + q * 4;
                float4 v = make_float4(0.f, 0.f, 0.f, 0.f);
                if (grow < NN) v = *(const float4*)(X + (size_t)grow * HIDD + kc + k);
                Xs[k + 0][lrow] = v.x;
                Xs[k + 1][lrow] = v.y;
                Xs[k + 2][lrow] = v.z;
                Xs[k + 3][lrow] = v.w;
            }
        }
        // W tile: 32 k x 128 cols, direct
#pragma unroll
        for (int v = 0; v < 4; v++) {
            int li = (tid + v * 256) * 4;
            int k = li >> 7, c = li & 127;
            *(float4*)(&Ws[k][c]) = *(const float4*)(W + (size_t)(kc + k) * HIDD + c);
        }
        __syncthreads();
#pragma unroll
        for (int kk = 0; kk < 32; kk++) {
            float xv[8], wv[8];
            *(float4*)&xv[0] = *(float4*)&Xs[kk][ty * 8];
            *(float4*)&xv[4] = *(float4*)&Xs[kk][ty * 8 + 4];
            *(float4*)&wv[0] = *(float4*)&Ws[kk][tx * 8];
            *(float4*)&wv[4] = *(float4*)&Ws[kk][tx * 8 + 4];
#pragma unroll
            for (int i = 0; i < 8; i++)
#pragma unroll
                for (int j = 0; j < 8; j++) acc[i][j] = fmaf(xv[i], wv[j], acc[i][j]);
        }
        __syncthreads();
    }

    float alv[8], arv[8];
#pragma unroll
    for (int j = 0; j < 8; j++) { alv[j] = attl[tx * 8 + j]; arv[j] = attr[tx * 8 + j]; }

#pragma unroll
    for (int i = 0; i < 8; i++) {
        int row = row0 + ty * 8 + i;
        if (row < NN) {
            *(float4*)(H + (size_t)row * HIDD + tx * 8)     = *(float4*)&acc[i][0];
            *(float4*)(H + (size_t)row * HIDD + tx * 8 + 4) = *(float4*)&acc[i][4];
            float ls = 0.f, rs = 0.f;
#pragma unroll
            for (int j = 0; j < 8; j++) {
                ls = fmaf(acc[i][j], alv[j], ls);
                rs = fmaf(acc[i][j], arv[j], rs);
            }
            // reduce over tx (16 lanes: xor offsets stay within the half-warp)
#pragma unroll
            for (int o = 8; o; o >>= 1) {
                ls += __shfl_xor_sync(0xFFFFFFFFu, ls, o);
                rs += __shfl_xor_sync(0xFFFFFFFFu, rs, o);
            }
            if (tx == 0) { Lo[row] = ls; Ro[row] = rs; }
        }
    }
}

// ---------------- CSR build --------------------------------------------------
__global__ void csr_zero_kernel() {
    int i = blockIdx.x * blockDim.x + threadIdx.x;
    if (i < NN) { g_cnt[i] = 0; g_cursor[i] = 0; }
}

__global__ void csr_count_kernel(const int* __restrict__ ei) {
    int e = blockIdx.x * blockDim.x + threadIdx.x;
    if (e >= EE) return;
    atomicAdd(&g_cnt[ei[EE + e]], 1);
}

__global__ void csr_scan_kernel() {
    __shared__ int wsum[32];
    __shared__ int carry;
    const int tid = threadIdx.x, lane = tid & 31, wid = tid >> 5;
    if (tid == 0) carry = 0;
    __syncthreads();
    for (int base = 0; base < NN; base += 1024) {
        int i = base + tid;
        int v = (i < NN) ? g_cnt[i] : 0;
        int x = v;
#pragma unroll
        for (int o = 1; o < 32; o <<= 1) {
            int y = __shfl_up_sync(0xFFFFFFFFu, x, o);
            if (lane >= o) x += y;
        }
        if (lane == 31) wsum[wid] = x;
        __syncthreads();
        if (wid == 0) {
            int s = wsum[lane];
#pragma unroll
            for (int o = 1; o < 32; o <<= 1) {
                int y = __shfl_up_sync(0xFFFFFFFFu, s, o);
                if (lane >= o) s += y;
            }
            wsum[lane] = s;
        }
        __syncthreads();
        int pre = (wid > 0 ? wsum[wid - 1] : 0) + carry;
        if (i < NN) g_start[i] = pre + x - v;
        int total = wsum[31];
        __syncthreads();
        if (tid == 0) carry += total;
        __syncthreads();
    }
    if (tid == 0) g_start[NN] = carry;
}

__global__ void csr_scatter_kernel(const int* __restrict__ ei) {
    int e = blockIdx.x * blockDim.x + threadIdx.x;
    if (e >= EE) return;
    int s = ei[e], d = ei[EE + e];
    int pos = g_start[d] + atomicAdd(&g_cursor[d], 1);
    g_csrc[pos] = s;
}

// ---------------- fused attention: warp per destination node ----------------
// no-max softmax (alpha bounded), 4-edge batches with software pipelining
__global__ __launch_bounds__(256) void attn_kernel(
        const float* __restrict__ H, const float* __restrict__ bias,
        int do_relu, float* __restrict__ out) {
    int n    = (blockIdx.x * blockDim.x + threadIdx.x) >> 5;
    int lane = threadIdx.x & 31;
    if (n >= NN) return;

    float4 hd = ((const float4*)(H + (size_t)n * HIDD))[lane];
    float Rd = g_R[n];
    float Ln = g_L[n];

    // self-loop
    float dp = hd.x * hd.x + hd.y * hd.y + hd.z * hd.z + hd.w * hd.w;
#pragma unroll
    for (int o = 16; o; o >>= 1) dp += __shfl_xor_sync(0xFFFFFFFFu, dp, o);
    float a0 = (Ln + Rd) * __frcp_rn(1.f + __expf(-dp));
    float w0 = __expf(a0);
    float den = w0;
    float4 acc = make_float4(w0 * hd.x, w0 * hd.y, w0 * hd.z, w0 * hd.w);

    const int beg = g_start[n], end = g_start[n + 1];
    int p = beg;
    float4 hs[4]; float Ls[4];
    if (p < end) {
        int nb = end - p; if (nb > 4) nb = 4;
#pragma unroll
        for (int j = 0; j < 4; j++) {
            int idx = p + (j < nb ? j : 0);
            int s = g_csrc[idx];
            hs[j] = ((const float4*)(H + (size_t)s * HIDD))[lane];
            Ls[j] = g_L[s];
        }
    }
    while (p < end) {
        int nb = end - p; if (nb > 4) nb = 4;
        float4 cs[4]; float cL[4];
#pragma unroll
        for (int j = 0; j < 4; j++) { cs[j] = hs[j]; cL[j] = Ls[j]; }
        int pn = p + nb;
        if (pn < end) {                       // prefetch next batch
            int nb2 = end - pn; if (nb2 > 4) nb2 = 4;
#pragma unroll
            for (int j = 0; j < 4; j++) {
                int idx = pn + (j < nb2 ? j : 0);
                int s = g_csrc[idx];
                hs[j] = ((const float4*)(H + (size_t)s * HIDD))[lane];
                Ls[j] = g_L[s];
            }
        }
        float d4[4];
#pragma unroll
        for (int j = 0; j < 4; j++)
            d4[j] = cs[j].x * hd.x + cs[j].y * hd.y + cs[j].z * hd.z + cs[j].w * hd.w;
#pragma unroll
        for (int o = 16; o; o >>= 1)
#pragma unroll
            for (int j = 0; j < 4; j++)
                d4[j] += __shfl_xor_sync(0xFFFFFFFFu, d4[j], o);
#pragma unroll
        for (int j = 0; j < 4; j++) {
            if (j < nb) {
                float a = (cL[j] + Rd) * __frcp_rn(1.f + __expf(-d4[j]));
                float w = __expf(a);
                den += w;
                acc.x = fmaf(w, cs[j].x, acc.x);
                acc.y = fmaf(w, cs[j].y, acc.y);
                acc.z = fmaf(w, cs[j].z, acc.z);
                acc.w = fmaf(w, cs[j].w, acc.w);
            }
        }
        p = pn;
    }

    float inv = 1.f / (den + 1e-16f);
    float4 b = ((const float4*)bias)[lane];
    float4 r;
    r.x = fmaf(acc.x, inv, b.x);
    r.y = fmaf(acc.y, inv, b.y);
    r.z = fmaf(acc.z, inv, b.z);
    r.w = fmaf(acc.w, inv, b.w);
    if (do_relu) {
        r.x = fmaxf(r.x, 0.f); r.y = fmaxf(r.y, 0.f);
        r.z = fmaxf(r.z, 0.f); r.w = fmaxf(r.w, 0.f);
    }
    ((float4*)(out + (size_t)n * HIDD))[lane] = r;
}

// ---------------- classifier decomposition: P = h@Wc[:128], Q = h@Wc[128:] --
__global__ void node_pq_kernel(const float* __restrict__ H,
                               const float* __restrict__ Wc) {
    int lane  = threadIdx.x & 31;
    int warp  = (blockIdx.x * blockDim.x + threadIdx.x) >> 5;
    int nwarp = (gridDim.x * blockDim.x) >> 5;
    float wt[4][4], wb[4][4];
#pragma unroll
    for (int i = 0; i < 4; i++)
#pragma unroll
        for (int o = 0; o < 4; o++) {
            wt[i][o] = Wc[(lane * 4 + i) * OUTD + o];
            wb[i][o] = Wc[(HIDD + lane * 4 + i) * OUTD + o];
        }
    for (int n = warp; n < NN; n += nwarp) {
        float4 hv = ((const float4*)(H + (size_t)n * HIDD))[lane];
        float h4[4] = {hv.x, hv.y, hv.z, hv.w};
        float pv[4] = {0.f, 0.f, 0.f, 0.f}, qv[4] = {0.f, 0.f, 0.f, 0.f};
#pragma unroll
        for (int i = 0; i < 4; i++)
#pragma unroll
            for (int o = 0; o < 4; o++) {
                pv[o] = fmaf(h4[i], wt[i][o], pv[o]);
                qv[o] = fmaf(h4[i], wb[i][o], qv[o]);
            }
#pragma unroll
        for (int o = 0; o < 4; o++)
#pragma unroll
            for (int off = 16; off; off >>= 1) {
                pv[o] += __shfl_xor_sync(0xFFFFFFFFu, pv[o], off);
                qv[o] += __shfl_xor_sync(0xFFFFFFFFu, qv[o], off);
            }
        if (lane == 0) {
            *(float4*)(g_P + (size_t)n * OUTD) = make_float4(pv[0], pv[1], pv[2], pv[3]);
            *(float4*)(g_Q + (size_t)n * OUTD) = make_float4(qv[0], qv[1], qv[2], qv[3]);
        }
    }
}

// ---------------- final per-edge output: out[e] = P[row] + Q[col] + bc ------
__global__ void edge_out_kernel(const int* __restrict__ ei,
                                const float* __restrict__ bc,
                                float* __restrict__ out) {
    int e = blockIdx.x * blockDim.x + threadIdx.x;
    if (e >= EE) return;
    int r = ei[e], c = ei[EE + e];
    float4 p = *(const float4*)(g_P + (size_t)r * OUTD);
    float4 q = *(const float4*)(g_Q + (size_t)c * OUTD);
    float b0 = bc[0], b1 = bc[1], b2 = bc[2], b3 = bc[3];
    *(float4*)(out + (size_t)e * OUTD) =
        make_float4(p.x + q.x + b0, p.y + q.y + b1, p.z + q.z + b2, p.w + q.w + b3);
}

// ---------------- launcher ---------------------------------------------------
extern "C" void kernel_launch(void* const* d_in, const int* in_sizes, int n_in,
                              void* d_out, int out_size) {
    const float* x   = (const float*)d_in[0];
    const int*   ei  = (const int*)d_in[1];
    const float* W1  = (const float*)d_in[2];
    const float* al1 = (const float*)d_in[3];
    const float* ar1 = (const float*)d_in[4];
    const float* b1  = (const float*)d_in[5];
    const float* W2  = (const float*)d_in[6];
    const float* al2 = (const float*)d_in[7];
    const float* ar2 = (const float*)d_in[8];
    const float* b2  = (const float*)d_in[9];
    const float* Wc  = (const float*)d_in[10];
    const float* bc  = (const float*)d_in[11];
    float* out = (float*)d_out;

    float *hA, *hB, *L, *R;
    cudaGetSymbolAddress((void**)&hA, g_hA);
    cudaGetSymbolAddress((void**)&hB, g_hB);
    cudaGetSymbolAddress((void**)&L,  g_L);
    cudaGetSymbolAddress((void**)&R,  g_R);

    const int TB = 256;
    const int gGemm = (NN + 127) / 128;               // 391
    const int gNode = (NN + TB - 1) / TB;             // 196
    const int gEdge = (EE + TB - 1) / TB;             // 3125
    const int gAttn = (NN * 32 + TB - 1) / TB;        // 6250 (warp per node)

    // ---- CSR build (by destination), reused by both layers ----
    csr_zero_kernel<<<gNode, TB>>>();
    csr_count_kernel<<<gEdge, TB>>>(ei);
    csr_scan_kernel<<<1, 1024>>>();
    csr_scatter_kernel<<<gEdge, TB>>>(ei);

    // ---- layer 1 ----
    gemm_lr_kernel<<<gGemm, TB>>>(x, W1, al1, ar1, hA, L, R);
    attn_kernel<<<gAttn, TB>>>(hA, b1, 1, hB);

    // ---- layer 2 ----
    gemm_lr_kernel<<<gGemm, TB>>>(hB, W2, al2, ar2, hA, L, R);
    attn_kernel<<<gAttn, TB>>>(hA, b2, 0, hB);

    // ---- edge classifier (decomposed) ----
    node_pq_kernel<<<1184, TB>>>(hB, Wc);
    edge_out_kernel<<<gEdge, TB>>>(ei, bc, out);
}